// round 14
// baseline (speedup 1.0000x reference)
#include <cuda_runtime.h>
#include <math.h>

typedef unsigned int       u32;
typedef unsigned long long u64;

// ---- problem constants ----
#define BW      1024
#define LW      144
#define CDIM    256
#define HEADS   8
#define DH      32
#define KDIM    256
#define NQKV    768
#define MH      384
#define LOGIT_MAX 4.605170185988091f
#define MROWS   (BW*LW)          // 147456
#define NWMAX   64

// ---- scratch (referenced ONLY inside device code) ----
__device__ float g_bias[HEADS*LW*LW];
__device__ float g_bm[HEADS*NWMAX*LW*LW];          // bias+mask fused
// x as bf16 hi/lo row-major
__device__ __align__(16) unsigned short g_xhi[MROWS*CDIM];
__device__ __align__(16) unsigned short g_xlo[MROWS*CDIM];
// q/k/v as bf16x2 hi/lo, normalized(+scaled) already: [(b*8+h)*144+l][16 u32]
__device__ __align__(16) u32 g_qh[BW*HEADS*LW*16];
__device__ __align__(16) u32 g_ql[BW*HEADS*LW*16];
__device__ __align__(16) u32 g_kh[BW*HEADS*LW*16];
__device__ __align__(16) u32 g_kl[BW*HEADS*LW*16];
__device__ __align__(16) u32 g_vh[BW*HEADS*LW*16];
__device__ __align__(16) u32 g_vl[BW*HEADS*LW*16];
// attention output bf16 hi/lo
__device__ __align__(16) unsigned short g_aoh[MROWS*CDIM];
__device__ __align__(16) unsigned short g_aol[MROWS*CDIM];
// weights pre-converted to B-fragment order: [nblock][kt][4096 u32]
__device__ __align__(16) u32 g_wqf[6*8*4096];
__device__ __align__(16) u32 g_wpf[2*8*4096];

// ============================================================
// helpers
// ============================================================
__device__ __forceinline__ float fast_exp(float x) {
    x = fmaxf(x, -87.0f);
    float y = x * 1.4426950408889634f;
    float n = rintf(y);
    float f = y - n;
    float p = 1.3333558146e-3f;
    p = fmaf(p, f, 9.6181291076e-3f);
    p = fmaf(p, f, 5.5504108664e-2f);
    p = fmaf(p, f, 2.4022650696e-1f);
    p = fmaf(p, f, 6.9314718056e-1f);
    p = fmaf(p, f, 1.0f);
    return p * __int_as_float(((int)n + 127) << 23);
}
__device__ __forceinline__ u32 smem_u32(const void* p) {
    u32 a;
    asm("{ .reg .u64 t; cvta.to.shared.u64 t, %1; cvt.u32.u64 %0, t; }" : "=r"(a) : "l"(p));
    return a;
}
__device__ __forceinline__ u32 bf16x2_rn(float lo, float hi) {
    u32 r; asm("cvt.rn.bf16x2.f32 %0, %1, %2;" : "=r"(r) : "f"(hi), "f"(lo)); return r;
}
__device__ __forceinline__ void ldsm4(u32* r, u32 addr) {
    asm volatile("ldmatrix.sync.aligned.m8n8.x4.shared.b16 {%0,%1,%2,%3}, [%4];"
        : "=r"(r[0]), "=r"(r[1]), "=r"(r[2]), "=r"(r[3]) : "r"(addr));
}
__device__ __forceinline__ void mma_bf16(float* d, const u32* a, u32 b0, u32 b1) {
    asm volatile("mma.sync.aligned.m16n8k16.row.col.f32.bf16.bf16.f32 "
        "{%0,%1,%2,%3}, {%4,%5,%6,%7}, {%8,%9}, {%0,%1,%2,%3};"
        : "+f"(d[0]), "+f"(d[1]), "+f"(d[2]), "+f"(d[3])
        : "r"(a[0]), "r"(a[1]), "r"(a[2]), "r"(a[3]), "r"(b0), "r"(b1));
}
__device__ __forceinline__ void cpa16(u32 dst, const void* src) {
    asm volatile("cp.async.cg.shared.global [%0], [%1], 16;" :: "r"(dst), "l"(src) : "memory");
}
__device__ __forceinline__ void split2(float x, float y, u32& h, u32& l) {
    h = bf16x2_rn(x, y);
    l = bf16x2_rn(x - __uint_as_float(h << 16), y - __uint_as_float(h & 0xFFFF0000u));
}

// ============================================================
// prep: convert x -> bf16 hi/lo row-major
// ============================================================
__global__ void convert_x_kernel(const float* __restrict__ x) {
    size_t idx = (size_t)blockIdx.x * 256 + threadIdx.x;   // one float4 each
    float4 v = ((const float4*)x)[idx];
    u32 h01, l01, h23, l23;
    split2(v.x, v.y, h01, l01);
    split2(v.z, v.w, h23, l23);
    ((uint2*)g_xhi)[idx] = make_uint2(h01, h23);
    ((uint2*)g_xlo)[idx] = make_uint2(l01, l23);
}

// ============================================================
// prep: convert weights -> B-fragment order bf16 hi/lo
// ============================================================
__global__ void convert_w_kernel(const float* __restrict__ W, int which, int total) {
    int i = blockIdx.x * 256 + threadIdx.x;
    if (i >= total) return;
    u32* dst = which ? g_wpf : g_wqf;
    int nb  = i >> 13;
    int rem = i & 8191;
    int row = rem >> 6;
    int kt  = (rem >> 3) & 7;
    int c4  = rem & 7;
    float4 v = *(const float4*)(W + (size_t)(nb * 128 + row) * KDIM + kt * 32 + c4 * 4);
    u32 h01, l01, h23, l23;
    split2(v.x, v.y, h01, l01);
    split2(v.z, v.w, h23, l23);
    int s = c4 >> 2, khalf = (c4 >> 1) & 1;
    int l = ((row & 7) << 2) + ((c4 & 1) << 1);
    int nt = row >> 3;
    u32* base = dst + (size_t)(nb * 8 + kt) * 4096 + ((s * 16 + nt) * 32 + l) * 4;
    base[khalf]     = h01;
    base[2 + khalf] = l01;
    base[4 + khalf] = h23;
    base[6 + khalf] = l23;
}

// ============================================================
// 1) bias table (meta MLP): one WARP per (i,j) point
// ============================================================
__global__ void __launch_bounds__(256)
bias_kernel(const float* __restrict__ fc1_w, const float* __restrict__ fc1_b,
            const float* __restrict__ fc2_w, const float* __restrict__ fc2_b) {
    int wid = threadIdx.x >> 5, lane = threadIdx.x & 31;
    int ij = blockIdx.x * 8 + wid;
    int i = ij / LW, j = ij % LW;
    float dy = (float)(i / 12 - j / 12);
    float dx = (float)(i % 12 - j % 12);
    float ry = copysignf(log1pf(fabsf(dy)), dy);
    float rx = copysignf(log1pf(fabsf(dx)), dx);

    float a[HEADS];
    #pragma unroll
    for (int hh = 0; hh < HEADS; hh++) a[hh] = 0.0f;
    for (int t = lane; t < MH; t += 32) {
        float hs = fmaf(fc1_w[2*t], ry, fmaf(fc1_w[2*t+1], rx, fc1_b[t]));
        hs = fmaxf(hs, 0.0f);
        #pragma unroll
        for (int hh = 0; hh < HEADS; hh++)
            a[hh] = fmaf(fc2_w[hh*MH + t], hs, a[hh]);
    }
    #pragma unroll
    for (int hh = 0; hh < HEADS; hh++) {
        #pragma unroll
        for (int o = 16; o; o >>= 1)
            a[hh] += __shfl_xor_sync(0xFFFFFFFFu, a[hh], o);
    }
    if (lane < HEADS) {
        float outv = a[0];
        #pragma unroll
        for (int hh = 1; hh < HEADS; hh++)
            if (lane == hh) outv = a[hh];
        g_bias[lane*LW*LW + ij] = outv + fc2_b[lane];
    }
}

// ============================================================
// 1b) fuse bias+mask
// ============================================================
__global__ void bm_kernel(const float* __restrict__ mask, int num_win, int total4) {
    int idx = blockIdx.x * 256 + threadIdx.x;
    if (idx >= total4) return;
    const int per = LW*LW/4;
    int hw = idx / per;
    int ij4 = idx % per;
    int h = hw / num_win, wi = hw % num_win;
    float4 bv = ((const float4*)(g_bias + h*LW*LW))[ij4];
    float4 mv = ((const float4*)(mask + (size_t)wi*LW*LW))[ij4];
    bv.x += mv.x; bv.y += mv.y; bv.z += mv.z; bv.w += mv.w;
    ((float4*)(g_bm + (size_t)hw*(LW*LW)))[ij4] = bv;
}

// ============================================================
// double-buffered cp.async GEMM mainloop (pre-converted operands)
// ============================================================
#define GSM_AHI    0
#define GSM_ALO    10240
#define GSM_BF     20480
#define GSM_STRIDE 36864
#define GEMM2_SMEM (2*GSM_STRIDE)

extern __shared__ char dynsm[];

__device__ __forceinline__ void gemm2_stage(const unsigned short* __restrict__ Ah,
                                            const unsigned short* __restrict__ Al,
                                            const u32* __restrict__ Wf,
                                            int m0, int kt, u32 s0) {
    int tid = threadIdx.x;
    #pragma unroll
    for (int j = 0; j < 2; j++) {
        int i = tid + j * 256;
        int r = i >> 2, c = i & 3;
        size_t so = (size_t)(m0 + r) * CDIM + kt * 32 + c * 8;
        cpa16(s0 + GSM_AHI + r * 80 + c * 16, Ah + so);
        cpa16(s0 + GSM_ALO + r * 80 + c * 16, Al + so);
    }
    const u32* wsrc = Wf + (size_t)kt * 4096;
    #pragma unroll
    for (int j = 0; j < 4; j++) {
        int i = tid + j * 256;
        cpa16(s0 + GSM_BF + i * 16, wsrc + i * 4);
    }
}

__device__ __forceinline__ void gemm2(const unsigned short* __restrict__ Ah,
                                      const unsigned short* __restrict__ Al,
                                      const u32* __restrict__ Wf,
                                      int m0, float acc[2][8][4]) {
    int tid = threadIdx.x, lane = tid & 31, wid = tid >> 5;
    int wm = wid >> 1, wn = wid & 1;

    #pragma unroll
    for (int mt = 0; mt < 2; mt++)
        #pragma unroll
        for (int nt = 0; nt < 8; nt++)
            #pragma unroll
            for (int c = 0; c < 4; c++) acc[mt][nt][c] = 0.0f;

    u32 sb = smem_u32(dynsm);
    gemm2_stage(Ah, Al, Wf, m0, 0, sb);
    asm volatile("cp.async.commit_group;" ::: "memory");

    for (int kt = 0; kt < 8; kt++) {
        if (kt < 7) {
            gemm2_stage(Ah, Al, Wf, m0, kt + 1, sb + ((kt + 1) & 1) * GSM_STRIDE);
            asm volatile("cp.async.commit_group;" ::: "memory");
            asm volatile("cp.async.wait_group 1;" ::: "memory");
        } else {
            asm volatile("cp.async.wait_group 0;" ::: "memory");
        }
        __syncthreads();

        u32 s0 = sb + (kt & 1) * GSM_STRIDE;
        u32 rowA = s0 + GSM_AHI + (wm * 32 + (lane & 15)) * 80 + ((lane >> 4) << 4);
        char* bfp = dynsm + (kt & 1) * GSM_STRIDE + GSM_BF;
        #pragma unroll
        for (int s = 0; s < 2; s++) {
            u32 ah[2][4], al[2][4];
            #pragma unroll
            for (int mt = 0; mt < 2; mt++) {
                u32 ad = rowA + mt * 16 * 80 + s * 32;
                ldsm4(ah[mt], ad);
                ldsm4(al[mt], ad + (GSM_ALO - GSM_AHI));
            }
            #pragma unroll
            for (int nt2 = 0; nt2 < 8; nt2++) {
                uint4 b = *(const uint4*)(bfp + (((s * 16 + wn * 8 + nt2) * 32 + lane) << 4));
                #pragma unroll
                for (int mt = 0; mt < 2; mt++) {
                    mma_bf16(acc[mt][nt2], ah[mt], b.x, b.y);
                    mma_bf16(acc[mt][nt2], al[mt], b.x, b.y);
                    mma_bf16(acc[mt][nt2], ah[mt], b.z, b.w);
                }
            }
        }
        __syncthreads();
    }
}

// ============================================================
// 2) QKV GEMM: epilogue does bias add + normalize + scale + bf16 split.
// ============================================================
__global__ void __launch_bounds__(256, 2)
qkv_mma_kernel(const float* __restrict__ bias, const float* __restrict__ logit_scale) {
    int m0 = blockIdx.y * 128;
    int n0b = blockIdx.x;
    float acc[2][8][4];
    gemm2(g_xhi, g_xlo, g_wqf + (size_t)n0b * 8 * 4096, m0, acc);

    int lane = threadIdx.x & 31, wid = threadIdx.x >> 5;
    int wm = wid >> 1, wn = wid & 1;
    int r = lane >> 2, c4l = lane & 3, cp = c4l * 2;
    int part = n0b >> 1;   // 0=q 1=k 2=v
    u32 *dh, *dl;
    if (part == 0)      { dh = g_qh; dl = g_ql; }
    else if (part == 1) { dh = g_kh; dl = g_kl; }
    else                { dh = g_vh; dl = g_vl; }

    #pragma unroll
    for (int mt = 0; mt < 2; mt++) {
        #pragma unroll
        for (int half = 0; half < 2; half++) {
            int m = m0 + wm * 32 + mt * 16 + r + half * 8;
            int b = m / LW, l = m % LW;
            #pragma unroll
            for (int g = 0; g < 2; g++) {
                int h = (n0b & 1) * 4 + wn * 2 + g;
                float v[8];
                #pragma unroll
                for (int j = 0; j < 4; j++) {
                    int col = n0b * 128 + wn * 64 + (g * 4 + j) * 8 + cp;
                    v[2*j]   = acc[mt][g*4+j][half*2]   + bias[col];
                    v[2*j+1] = acc[mt][g*4+j][half*2+1] + bias[col+1];
                }
                float inv = 1.0f;
                if (part < 2) {
                    float ss = 0.0f;
                    #pragma unroll
                    for (int q = 0; q < 8; q++) ss = fmaf(v[q], v[q], ss);
                    ss += __shfl_xor_sync(0xFFFFFFFFu, ss, 1);
                    ss += __shfl_xor_sync(0xFFFFFFFFu, ss, 2);
                    inv = 1.0f / fmaxf(sqrtf(ss), 1e-12f);
                    if (part == 0)
                        inv *= fast_exp(fminf(logit_scale[h], LOGIT_MAX));
                }
                size_t row = (size_t)(b * HEADS + h) * LW + l;
                #pragma unroll
                for (int j = 0; j < 4; j++) {
                    u32 hh, ll;
                    split2(v[2*j] * inv, v[2*j+1] * inv, hh, ll);
                    dh[row * 16 + j * 4 + c4l] = hh;
                    dl[row * 16 + j * 4 + c4l] = ll;
                }
            }
        }
    }
}

// ============================================================
// 3) Attention: flash-style mma.sync bf16x3; bm loads fused into S-MMA loop
// ============================================================
#define QPITCH 80
#define VPITCH 304
#define OQH 0
#define OQL 11520
#define OKF 23040
#define OVH 41472
#define OVL 51200
#define ATTN_SMEM 60928

__global__ void __launch_bounds__(160)
attn_mma_kernel(int num_win) {
    extern __shared__ char sm[];
    char* sQh = sm + OQH;
    char* sQl = sm + OQL;
    char* sKf = sm + OKF;
    char* sVh = sm + OVH;
    char* sVl = sm + OVL;

    int h = blockIdx.x & 7;
    int b = blockIdx.x >> 3;
    int tid = threadIdx.x;

    if (tid < LW) {
        int r = tid;
        size_t row = (size_t)(b * HEADS + h) * LW + r;
        const uint2* kh = (const uint2*)(g_kh + row * 16);
        const uint2* kl = (const uint2*)(g_kl + row * 16);
        #pragma unroll
        for (int c4 = 0; c4 < 8; c4++) {
            uint2 vh = kh[c4], vl = kl[c4];
            int s = c4 >> 2, khalf = (c4 >> 1) & 1;
            int l = ((r & 7) << 2) + ((c4 & 1) << 1);
            int nt = r >> 3;
            char* p = sKf + (((s * 18 + nt) * 32 + l) << 4);
            *(u32*)(p + khalf * 4)      = vh.x;
            *(u32*)(p + 8 + khalf * 4)  = vl.x;
            *(u32*)(p + 16 + khalf * 4) = vh.y;
            *(u32*)(p + 24 + khalf * 4) = vl.y;
        }
        const uint2* qh = (const uint2*)(g_qh + row * 16);
        const uint2* ql = (const uint2*)(g_ql + row * 16);
        #pragma unroll
        for (int c4 = 0; c4 < 8; c4++) {
            *(uint2*)(sQh + r * QPITCH + c4 * 8) = qh[c4];
            *(uint2*)(sQl + r * QPITCH + c4 * 8) = ql[c4];
        }
        const uint2* vhp = (const uint2*)(g_vh + row * 16);
        const uint2* vlp = (const uint2*)(g_vl + row * 16);
        #pragma unroll
        for (int c4 = 0; c4 < 8; c4++) {
            uint2 hv = vhp[c4], lv = vlp[c4];
            int d = c4 * 4;
            *(unsigned short*)(sVh + (d+0)*VPITCH + r*2) = (unsigned short)(hv.x & 0xFFFFu);
            *(unsigned short*)(sVh + (d+1)*VPITCH + r*2) = (unsigned short)(hv.x >> 16);
            *(unsigned short*)(sVh + (d+2)*VPITCH + r*2) = (unsigned short)(hv.y & 0xFFFFu);
            *(unsigned short*)(sVh + (d+3)*VPITCH + r*2) = (unsigned short)(hv.y >> 16);
            *(unsigned short*)(sVl + (d+0)*VPITCH + r*2) = (unsigned short)(lv.x & 0xFFFFu);
            *(unsigned short*)(sVl + (d+1)*VPITCH + r*2) = (unsigned short)(lv.x >> 16);
            *(unsigned short*)(sVl + (d+2)*VPITCH + r*2) = (unsigned short)(lv.y & 0xFFFFu);
            *(unsigned short*)(sVl + (d+3)*VPITCH + r*2) = (unsigned short)(lv.y >> 16);
        }
    }
    __syncthreads();

    int lane = tid & 31, w = tid >> 5;
    int r4 = lane >> 2, c4l = lane & 3;
    int mstart = 2 * w;
    int mcount = (w == 4) ? 1 : 2;
    int wi = b % num_win;
    u32 aQh = smem_u32(sQh), aQl = smem_u32(sQl);

    for (int mi = 0; mi < mcount; mi++) {
        int mt = mstart + mi;
        int row0 = mt * 16 + r4;

        u32 qh[2][4], ql[2][4];
        u32 arow = (u32)((mt * 16 + (lane & 15)) * QPITCH + ((lane >> 4) << 4));
        ldsm4(qh[0], aQh + arow);
        ldsm4(qh[1], aQh + arow + 32);
        ldsm4(ql[0], aQl + arow);
        ldsm4(ql[1], aQl + arow + 32);

        const float* bm0 = g_bm + (((size_t)h * num_win + wi) * LW + row0) * LW;
        const float* bm1 = bm0 + 8 * LW;

        // S = Qn*Kn^T with bm load+add+max FUSED per j (loads independent of
        // MMA results -> ptxas overlaps the L2 latency with tensor work)
        float sfr[18][4];
        float mx0 = -1e30f, mx1 = -1e30f;
        #pragma unroll
        for (int j = 0; j < 18; j++) {
            #pragma unroll
            for (int q = 0; q < 4; q++) sfr[j][q] = 0.0f;
            #pragma unroll
            for (int s = 0; s < 2; s++) {
                uint4 bb = *(const uint4*)(sKf + (((s * 18 + j) * 32 + lane) << 4));
                mma_bf16(sfr[j], qh[s], bb.x, bb.y);
                mma_bf16(sfr[j], ql[s], bb.x, bb.y);
                mma_bf16(sfr[j], qh[s], bb.z, bb.w);
            }
            int col = j * 8 + c4l * 2;
            float2 b0 = *(const float2*)(bm0 + col);
            float2 b1 = *(const float2*)(bm1 + col);
            sfr[j][0] += b0.x; sfr[j][1] += b0.y;
            sfr[j][2] += b1.x; sfr[j][3] += b1.y;
            mx0 = fmaxf(mx0, fmaxf(sfr[j][0], sfr[j][1]));
            mx1 = fmaxf(mx1, fmaxf(sfr[j][2], sfr[j][3]));
        }
        mx0 = fmaxf(mx0, __shfl_xor_sync(0xFFFFFFFFu, mx0, 1));
        mx0 = fmaxf(mx0, __shfl_xor_sync(0xFFFFFFFFu, mx0, 2));
        mx1 = fmaxf(mx1, __shfl_xor_sync(0xFFFFFFFFu, mx1, 1));
        mx1 = fmaxf(mx1, __shfl_xor_sync(0xFFFFFFFFu, mx1, 2));

        float sum0 = 0.0f, sum1 = 0.0f;
        #pragma unroll
        for (int j = 0; j < 18; j++) {
            float p0 = fast_exp(sfr[j][0] - mx0);
            float p1 = fast_exp(sfr[j][1] - mx0);
            float p2 = fast_exp(sfr[j][2] - mx1);
            float p3 = fast_exp(sfr[j][3] - mx1);
            sfr[j][0] = p0; sfr[j][1] = p1; sfr[j][2] = p2; sfr[j][3] = p3;
            sum0 += p0 + p1; sum1 += p2 + p3;
        }
        sum0 += __shfl_xor_sync(0xFFFFFFFFu, sum0, 1);
        sum0 += __shfl_xor_sync(0xFFFFFFFFu, sum0, 2);
        sum1 += __shfl_xor_sync(0xFFFFFFFFu, sum1, 1);
        sum1 += __shfl_xor_sync(0xFFFFFFFFu, sum1, 2);

        float o[4][4];
        #pragma unroll
        for (int n = 0; n < 4; n++)
            #pragma unroll
            for (int q = 0; q < 4; q++) o[n][q] = 0.0f;

        #pragma unroll
        for (int t = 0; t < 9; t++) {
            u32 ph[4], pl[4];
            ph[0] = bf16x2_rn(sfr[2*t][0], sfr[2*t][1]);
            ph[1] = bf16x2_rn(sfr[2*t][2], sfr[2*t][3]);
            ph[2] = bf16x2_rn(sfr[2*t+1][0], sfr[2*t+1][1]);
            ph[3] = bf16x2_rn(sfr[2*t+1][2], sfr[2*t+1][3]);
            pl[0] = bf16x2_rn(sfr[2*t][0]   - __uint_as_float(ph[0] << 16),
                              sfr[2*t][1]   - __uint_as_float(ph[0] & 0xFFFF0000u));
            pl[1] = bf16x2_rn(sfr[2*t][2]   - __uint_as_float(ph[1] << 16),
                              sfr[2*t][3]   - __uint_as_float(ph[1] & 0xFFFF0000u));
            pl[2] = bf16x2_rn(sfr[2*t+1][0] - __uint_as_float(ph[2] << 16),
                              sfr[2*t+1][1] - __uint_as_float(ph[2] & 0xFFFF0000u));
            pl[3] = bf16x2_rn(sfr[2*t+1][2] - __uint_as_float(ph[3] << 16),
                              sfr[2*t+1][3] - __uint_as_float(ph[3] & 0xFFFF0000u));
            int kb = t * 32 + c4l * 4;
            #pragma unroll
            for (int n = 0; n < 4; n++) {
                int vrow = (n * 8 + r4) * VPITCH;
                u32 b0h = *(const u32*)(sVh + vrow + kb);
                u32 b1h = *(const u32*)(sVh + vrow + kb + 16);
                u32 b0l = *(const u32*)(sVl + vrow + kb);
                u32 b1l = *(const u32*)(sVl + vrow + kb + 16);
                mma_bf16(o[n], ph, b0h, b1h);
                mma_bf16(o[n], pl, b0h, b1h);
                mma_bf16(o[n], ph, b0l, b1l);
            }
        }

        float i0 = 1.0f / sum0, i1 = 1.0f / sum1;
        int m0r = b * LW + row0;
        int colb = h * DH + c4l * 2;
        #pragma unroll
        for (int n = 0; n < 4; n++) {
            int col = colb + n * 8;
            u32 hh, ll;
            split2(o[n][0] * i0, o[n][1] * i0, hh, ll);
            ((u32*)g_aoh)[(size_t)m0r * 128 + (col >> 1)] = hh;
            ((u32*)g_aol)[(size_t)m0r * 128 + (col >> 1)] = ll;
            split2(o[n][2] * i1, o[n][3] * i1, hh, ll);
            ((u32*)g_aoh)[(size_t)(m0r + 8) * 128 + (col >> 1)] = hh;
            ((u32*)g_aol)[(size_t)(m0r + 8) * 128 + (col >> 1)] = ll;
        }
    }
}

// ============================================================
// 4) Output projection
// ============================================================
__global__ void __launch_bounds__(256, 2)
proj_mma_kernel(const float* __restrict__ bias, float* __restrict__ out) {
    int m0 = blockIdx.y * 128;
    int n0b = blockIdx.x;
    float acc[2][8][4];
    gemm2(g_aoh, g_aol, g_wpf + (size_t)n0b * 8 * 4096, m0, acc);

    int lane = threadIdx.x & 31, wid = threadIdx.x >> 5;
    int wm = wid >> 1, wn = wid & 1;
    int r = lane >> 2, cp = (lane & 3) * 2;

    #pragma unroll
    for (int mt = 0; mt < 2; mt++) {
        #pragma unroll
        for (int half = 0; half < 2; half++) {
            int m = m0 + wm * 32 + mt * 16 + r + half * 8;
            #pragma unroll
            for (int nt2 = 0; nt2 < 8; nt2++) {
                int col = n0b * 128 + wn * 64 + nt2 * 8 + cp;
                float2 v;
                v.x = acc[mt][nt2][half * 2 + 0] + bias[col];
                v.y = acc[mt][nt2][half * 2 + 1] + bias[col + 1];
                *(float2*)(out + (size_t)m * CDIM + col) = v;
            }
        }
    }
}

// ============================================================
// launch
// ============================================================
extern "C" void kernel_launch(void* const* d_in, const int* in_sizes, int n_in,
                              void* d_out, int out_size) {
    const float* x           = (const float*)d_in[0];
    const float* mask        = (const float*)d_in[1];
    const float* qkv_w       = (const float*)d_in[2];
    const float* qkv_b       = (const float*)d_in[3];
    const float* proj_w      = (const float*)d_in[4];
    const float* proj_b      = (const float*)d_in[5];
    const float* fc1_w       = (const float*)d_in[6];
    const float* fc1_b       = (const float*)d_in[7];
    const float* fc2_w       = (const float*)d_in[8];
    const float* fc2_b       = (const float*)d_in[9];
    const float* logit_scale = (const float*)d_in[10];

    int Bw = in_sizes[0] / (LW * CDIM);       // 1024
    int num_win = in_sizes[1] / (LW * LW);    // 64
    int Mrows = Bw * LW;                      // 147456

    static int attr_set = 0;
    if (!attr_set) {
        cudaFuncSetAttribute(attn_mma_kernel,
                             cudaFuncAttributeMaxDynamicSharedMemorySize, ATTN_SMEM);
        cudaFuncSetAttribute(qkv_mma_kernel,
                             cudaFuncAttributeMaxDynamicSharedMemorySize, GEMM2_SMEM);
        cudaFuncSetAttribute(proj_mma_kernel,
                             cudaFuncAttributeMaxDynamicSharedMemorySize, GEMM2_SMEM);
        attr_set = 1;
    }

    int bm_total4 = HEADS * num_win * (LW * LW / 4);

    convert_x_kernel<<<(Mrows * (CDIM/4)) / 256, 256>>>(x);
    convert_w_kernel<<<(6 * 8192 + 255) / 256, 256>>>(qkv_w, 0, 6 * 8192);
    convert_w_kernel<<<(2 * 8192 + 255) / 256, 256>>>(proj_w, 1, 2 * 8192);
    bias_kernel<<<(LW*LW) / 8, 256>>>(fc1_w, fc1_b, fc2_w, fc2_b);
    bm_kernel<<<(bm_total4 + 255) / 256, 256>>>(mask, num_win, bm_total4);
    qkv_mma_kernel<<<dim3(NQKV / 128, Mrows / 128), 256, GEMM2_SMEM>>>(qkv_b, logit_scale);
    attn_mma_kernel<<<Bw * HEADS, 160, ATTN_SMEM>>>(num_win);
    proj_mma_kernel<<<dim3(CDIM / 128, Mrows / 128), 256, GEMM2_SMEM>>>(proj_b, (float*)d_out);
}

// round 15
// speedup vs baseline: 1.5158x; 1.5158x over previous
#include <cuda_runtime.h>
#include <math.h>

typedef unsigned int       u32;
typedef unsigned long long u64;

// ---- problem constants ----
#define BW      1024
#define LW      144
#define CDIM    256
#define HEADS   8
#define DH      32
#define KDIM    256
#define NQKV    768
#define MH      384
#define LOGIT_MAX 4.605170185988091f
#define MROWS   (BW*LW)          // 147456
#define NWMAX   64

// ---- scratch (referenced ONLY inside device code) ----
__device__ float g_bias[HEADS*LW*LW];
__device__ float g_bm[HEADS*NWMAX*LW*LW];          // bias+mask fused
// x as bf16 hi/lo row-major
__device__ __align__(16) unsigned short g_xhi[MROWS*CDIM];
__device__ __align__(16) unsigned short g_xlo[MROWS*CDIM];
// q/k/v as bf16x2 hi/lo, normalized(+scaled) already: [(b*8+h)*144+l][16 u32]
__device__ __align__(16) u32 g_qh[BW*HEADS*LW*16];
__device__ __align__(16) u32 g_ql[BW*HEADS*LW*16];
__device__ __align__(16) u32 g_kh[BW*HEADS*LW*16];
__device__ __align__(16) u32 g_kl[BW*HEADS*LW*16];
__device__ __align__(16) u32 g_vh[BW*HEADS*LW*16];
__device__ __align__(16) u32 g_vl[BW*HEADS*LW*16];
// attention output bf16 hi/lo
__device__ __align__(16) unsigned short g_aoh[MROWS*CDIM];
__device__ __align__(16) unsigned short g_aol[MROWS*CDIM];
// weights pre-converted to B-fragment order: [nblock][kt][4096 u32]
__device__ __align__(16) u32 g_wqf[6*8*4096];
__device__ __align__(16) u32 g_wpf[2*8*4096];

// ============================================================
// helpers
// ============================================================
__device__ __forceinline__ float fast_exp(float x) {
    x = fmaxf(x, -87.0f);
    float y = x * 1.4426950408889634f;
    float n = rintf(y);
    float f = y - n;
    float p = 1.3333558146e-3f;
    p = fmaf(p, f, 9.6181291076e-3f);
    p = fmaf(p, f, 5.5504108664e-2f);
    p = fmaf(p, f, 2.4022650696e-1f);
    p = fmaf(p, f, 6.9314718056e-1f);
    p = fmaf(p, f, 1.0f);
    return p * __int_as_float(((int)n + 127) << 23);
}
__device__ __forceinline__ u32 smem_u32(const void* p) {
    u32 a;
    asm("{ .reg .u64 t; cvta.to.shared.u64 t, %1; cvt.u32.u64 %0, t; }" : "=r"(a) : "l"(p));
    return a;
}
__device__ __forceinline__ u32 bf16x2_rn(float lo, float hi) {
    u32 r; asm("cvt.rn.bf16x2.f32 %0, %1, %2;" : "=r"(r) : "f"(hi), "f"(lo)); return r;
}
__device__ __forceinline__ void ldsm4(u32* r, u32 addr) {
    asm volatile("ldmatrix.sync.aligned.m8n8.x4.shared.b16 {%0,%1,%2,%3}, [%4];"
        : "=r"(r[0]), "=r"(r[1]), "=r"(r[2]), "=r"(r[3]) : "r"(addr));
}
__device__ __forceinline__ void mma_bf16(float* d, const u32* a, u32 b0, u32 b1) {
    asm volatile("mma.sync.aligned.m16n8k16.row.col.f32.bf16.bf16.f32 "
        "{%0,%1,%2,%3}, {%4,%5,%6,%7}, {%8,%9}, {%0,%1,%2,%3};"
        : "+f"(d[0]), "+f"(d[1]), "+f"(d[2]), "+f"(d[3])
        : "r"(a[0]), "r"(a[1]), "r"(a[2]), "r"(a[3]), "r"(b0), "r"(b1));
}
__device__ __forceinline__ void cpa16(u32 dst, const void* src) {
    asm volatile("cp.async.cg.shared.global [%0], [%1], 16;" :: "r"(dst), "l"(src) : "memory");
}
__device__ __forceinline__ void split2(float x, float y, u32& h, u32& l) {
    h = bf16x2_rn(x, y);
    l = bf16x2_rn(x - __uint_as_float(h << 16), y - __uint_as_float(h & 0xFFFF0000u));
}

// ============================================================
// fused prep kernel: blockIdx ranges
//   [0, 36864)                : convert x -> bf16 hi/lo
//   [36864, 37056)            : convert qkv_w -> fragment order
//   [37056, 37120)            : convert proj_w -> fragment order
//   [37120, 39712)            : bias table (one warp per (i,j))
// ============================================================
#define PREP_X_BLKS   36864
#define PREP_WQ_BLKS  192
#define PREP_WP_BLKS  64
#define PREP_B_BLKS   2592
#define PREP_GRID     (PREP_X_BLKS + PREP_WQ_BLKS + PREP_WP_BLKS + PREP_B_BLKS)

__device__ __forceinline__ void convert_w_body(const float* __restrict__ W,
                                               u32* __restrict__ dst, int i) {
    int nb  = i >> 13;
    int rem = i & 8191;
    int row = rem >> 6;
    int kt  = (rem >> 3) & 7;
    int c4  = rem & 7;
    float4 v = *(const float4*)(W + (size_t)(nb * 128 + row) * KDIM + kt * 32 + c4 * 4);
    u32 h01, l01, h23, l23;
    split2(v.x, v.y, h01, l01);
    split2(v.z, v.w, h23, l23);
    int s = c4 >> 2, khalf = (c4 >> 1) & 1;
    int l = ((row & 7) << 2) + ((c4 & 1) << 1);
    int nt = row >> 3;
    u32* base = dst + (size_t)(nb * 8 + kt) * 4096 + ((s * 16 + nt) * 32 + l) * 4;
    base[khalf]     = h01;
    base[2 + khalf] = l01;
    base[4 + khalf] = h23;
    base[6 + khalf] = l23;
}

__global__ void __launch_bounds__(256)
prep_kernel(const float* __restrict__ x,
            const float* __restrict__ qkv_w, const float* __restrict__ proj_w,
            const float* __restrict__ fc1_w, const float* __restrict__ fc1_b,
            const float* __restrict__ fc2_w, const float* __restrict__ fc2_b) {
    int bid = blockIdx.x;
    int tid = threadIdx.x;

    if (bid < PREP_X_BLKS) {
        // ---- convert x ----
        size_t idx = (size_t)bid * 256 + tid;
        float4 v = ((const float4*)x)[idx];
        u32 h01, l01, h23, l23;
        split2(v.x, v.y, h01, l01);
        split2(v.z, v.w, h23, l23);
        ((uint2*)g_xhi)[idx] = make_uint2(h01, h23);
        ((uint2*)g_xlo)[idx] = make_uint2(l01, l23);
        return;
    }
    bid -= PREP_X_BLKS;
    if (bid < PREP_WQ_BLKS) {
        convert_w_body(qkv_w, g_wqf, bid * 256 + tid);
        return;
    }
    bid -= PREP_WQ_BLKS;
    if (bid < PREP_WP_BLKS) {
        convert_w_body(proj_w, g_wpf, bid * 256 + tid);
        return;
    }
    bid -= PREP_WP_BLKS;
    {
        // ---- bias table: one warp per (i,j) ----
        int wid = tid >> 5, lane = tid & 31;
        int ij = bid * 8 + wid;
        int i = ij / LW, j = ij % LW;
        float dy = (float)(i / 12 - j / 12);
        float dx = (float)(i % 12 - j % 12);
        float ry = copysignf(log1pf(fabsf(dy)), dy);
        float rx = copysignf(log1pf(fabsf(dx)), dx);

        float a[HEADS];
        #pragma unroll
        for (int hh = 0; hh < HEADS; hh++) a[hh] = 0.0f;
        for (int t = lane; t < MH; t += 32) {
            float hs = fmaf(fc1_w[2*t], ry, fmaf(fc1_w[2*t+1], rx, fc1_b[t]));
            hs = fmaxf(hs, 0.0f);
            #pragma unroll
            for (int hh = 0; hh < HEADS; hh++)
                a[hh] = fmaf(fc2_w[hh*MH + t], hs, a[hh]);
        }
        #pragma unroll
        for (int hh = 0; hh < HEADS; hh++) {
            #pragma unroll
            for (int o = 16; o; o >>= 1)
                a[hh] += __shfl_xor_sync(0xFFFFFFFFu, a[hh], o);
        }
        if (lane < HEADS) {
            float outv = a[0];
            #pragma unroll
            for (int hh = 1; hh < HEADS; hh++)
                if (lane == hh) outv = a[hh];
            g_bias[lane*LW*LW + ij] = outv + fc2_b[lane];
        }
    }
}

// ============================================================
// 1b) fuse bias+mask
// ============================================================
__global__ void bm_kernel(const float* __restrict__ mask, int num_win, int total4) {
    int idx = blockIdx.x * 256 + threadIdx.x;
    if (idx >= total4) return;
    const int per = LW*LW/4;
    int hw = idx / per;
    int ij4 = idx % per;
    int h = hw / num_win, wi = hw % num_win;
    float4 bv = ((const float4*)(g_bias + h*LW*LW))[ij4];
    float4 mv = ((const float4*)(mask + (size_t)wi*LW*LW))[ij4];
    bv.x += mv.x; bv.y += mv.y; bv.z += mv.z; bv.w += mv.w;
    ((float4*)(g_bm + (size_t)hw*(LW*LW)))[ij4] = bv;
}

// ============================================================
// double-buffered cp.async GEMM mainloop (pre-converted operands)
// ============================================================
#define GSM_AHI    0
#define GSM_ALO    10240
#define GSM_BF     20480
#define GSM_STRIDE 36864
#define GEMM2_SMEM (2*GSM_STRIDE)

extern __shared__ char dynsm[];

__device__ __forceinline__ void gemm2_stage(const unsigned short* __restrict__ Ah,
                                            const unsigned short* __restrict__ Al,
                                            const u32* __restrict__ Wf,
                                            int m0, int kt, u32 s0) {
    int tid = threadIdx.x;
    #pragma unroll
    for (int j = 0; j < 2; j++) {
        int i = tid + j * 256;
        int r = i >> 2, c = i & 3;
        size_t so = (size_t)(m0 + r) * CDIM + kt * 32 + c * 8;
        cpa16(s0 + GSM_AHI + r * 80 + c * 16, Ah + so);
        cpa16(s0 + GSM_ALO + r * 80 + c * 16, Al + so);
    }
    const u32* wsrc = Wf + (size_t)kt * 4096;
    #pragma unroll
    for (int j = 0; j < 4; j++) {
        int i = tid + j * 256;
        cpa16(s0 + GSM_BF + i * 16, wsrc + i * 4);
    }
}

__device__ __forceinline__ void gemm2(const unsigned short* __restrict__ Ah,
                                      const unsigned short* __restrict__ Al,
                                      const u32* __restrict__ Wf,
                                      int m0, float acc[2][8][4]) {
    int tid = threadIdx.x, lane = tid & 31, wid = tid >> 5;
    int wm = wid >> 1, wn = wid & 1;

    #pragma unroll
    for (int mt = 0; mt < 2; mt++)
        #pragma unroll
        for (int nt = 0; nt < 8; nt++)
            #pragma unroll
            for (int c = 0; c < 4; c++) acc[mt][nt][c] = 0.0f;

    u32 sb = smem_u32(dynsm);
    gemm2_stage(Ah, Al, Wf, m0, 0, sb);
    asm volatile("cp.async.commit_group;" ::: "memory");

    for (int kt = 0; kt < 8; kt++) {
        if (kt < 7) {
            gemm2_stage(Ah, Al, Wf, m0, kt + 1, sb + ((kt + 1) & 1) * GSM_STRIDE);
            asm volatile("cp.async.commit_group;" ::: "memory");
            asm volatile("cp.async.wait_group 1;" ::: "memory");
        } else {
            asm volatile("cp.async.wait_group 0;" ::: "memory");
        }
        __syncthreads();

        u32 s0 = sb + (kt & 1) * GSM_STRIDE;
        u32 rowA = s0 + GSM_AHI + (wm * 32 + (lane & 15)) * 80 + ((lane >> 4) << 4);
        char* bfp = dynsm + (kt & 1) * GSM_STRIDE + GSM_BF;
        #pragma unroll
        for (int s = 0; s < 2; s++) {
            u32 ah[2][4], al[2][4];
            #pragma unroll
            for (int mt = 0; mt < 2; mt++) {
                u32 ad = rowA + mt * 16 * 80 + s * 32;
                ldsm4(ah[mt], ad);
                ldsm4(al[mt], ad + (GSM_ALO - GSM_AHI));
            }
            #pragma unroll
            for (int nt2 = 0; nt2 < 8; nt2++) {
                uint4 b = *(const uint4*)(bfp + (((s * 16 + wn * 8 + nt2) * 32 + lane) << 4));
                #pragma unroll
                for (int mt = 0; mt < 2; mt++) {
                    mma_bf16(acc[mt][nt2], ah[mt], b.x, b.y);
                    mma_bf16(acc[mt][nt2], al[mt], b.x, b.y);
                    mma_bf16(acc[mt][nt2], ah[mt], b.z, b.w);
                }
            }
        }
        __syncthreads();
    }
}

// ============================================================
// 2) QKV GEMM: epilogue does bias add + normalize + scale + bf16 split.
// ============================================================
__global__ void __launch_bounds__(256, 2)
qkv_mma_kernel(const float* __restrict__ bias, const float* __restrict__ logit_scale) {
    int m0 = blockIdx.y * 128;
    int n0b = blockIdx.x;
    float acc[2][8][4];
    gemm2(g_xhi, g_xlo, g_wqf + (size_t)n0b * 8 * 4096, m0, acc);

    int lane = threadIdx.x & 31, wid = threadIdx.x >> 5;
    int wm = wid >> 1, wn = wid & 1;
    int r = lane >> 2, c4l = lane & 3, cp = c4l * 2;
    int part = n0b >> 1;   // 0=q 1=k 2=v
    u32 *dh, *dl;
    if (part == 0)      { dh = g_qh; dl = g_ql; }
    else if (part == 1) { dh = g_kh; dl = g_kl; }
    else                { dh = g_vh; dl = g_vl; }

    #pragma unroll
    for (int mt = 0; mt < 2; mt++) {
        #pragma unroll
        for (int half = 0; half < 2; half++) {
            int m = m0 + wm * 32 + mt * 16 + r + half * 8;
            int b = m / LW, l = m % LW;
            #pragma unroll
            for (int g = 0; g < 2; g++) {
                int h = (n0b & 1) * 4 + wn * 2 + g;
                float v[8];
                #pragma unroll
                for (int j = 0; j < 4; j++) {
                    int col = n0b * 128 + wn * 64 + (g * 4 + j) * 8 + cp;
                    v[2*j]   = acc[mt][g*4+j][half*2]   + bias[col];
                    v[2*j+1] = acc[mt][g*4+j][half*2+1] + bias[col+1];
                }
                float inv = 1.0f;
                if (part < 2) {
                    float ss = 0.0f;
                    #pragma unroll
                    for (int q = 0; q < 8; q++) ss = fmaf(v[q], v[q], ss);
                    ss += __shfl_xor_sync(0xFFFFFFFFu, ss, 1);
                    ss += __shfl_xor_sync(0xFFFFFFFFu, ss, 2);
                    inv = 1.0f / fmaxf(sqrtf(ss), 1e-12f);
                    if (part == 0)
                        inv *= fast_exp(fminf(logit_scale[h], LOGIT_MAX));
                }
                size_t row = (size_t)(b * HEADS + h) * LW + l;
                #pragma unroll
                for (int j = 0; j < 4; j++) {
                    u32 hh, ll;
                    split2(v[2*j] * inv, v[2*j+1] * inv, hh, ll);
                    dh[row * 16 + j * 4 + c4l] = hh;
                    dl[row * 16 + j * 4 + c4l] = ll;
                }
            }
        }
    }
}

// ============================================================
// 3) Attention: flash-style mma.sync bf16x3 (R12 form, verbatim)
// ============================================================
#define QPITCH 80
#define VPITCH 304
#define OQH 0
#define OQL 11520
#define OKF 23040
#define OVH 41472
#define OVL 51200
#define ATTN_SMEM 60928

__global__ void __launch_bounds__(160)
attn_mma_kernel(int num_win) {
    extern __shared__ char sm[];
    char* sQh = sm + OQH;
    char* sQl = sm + OQL;
    char* sKf = sm + OKF;
    char* sVh = sm + OVH;
    char* sVl = sm + OVL;

    int h = blockIdx.x & 7;
    int b = blockIdx.x >> 3;
    int tid = threadIdx.x;

    if (tid < LW) {
        int r = tid;
        size_t row = (size_t)(b * HEADS + h) * LW + r;
        const uint2* kh = (const uint2*)(g_kh + row * 16);
        const uint2* kl = (const uint2*)(g_kl + row * 16);
        #pragma unroll
        for (int c4 = 0; c4 < 8; c4++) {
            uint2 vh = kh[c4], vl = kl[c4];
            int s = c4 >> 2, khalf = (c4 >> 1) & 1;
            int l = ((r & 7) << 2) + ((c4 & 1) << 1);
            int nt = r >> 3;
            char* p = sKf + (((s * 18 + nt) * 32 + l) << 4);
            *(u32*)(p + khalf * 4)      = vh.x;
            *(u32*)(p + 8 + khalf * 4)  = vl.x;
            *(u32*)(p + 16 + khalf * 4) = vh.y;
            *(u32*)(p + 24 + khalf * 4) = vl.y;
        }
        const uint2* qh = (const uint2*)(g_qh + row * 16);
        const uint2* ql = (const uint2*)(g_ql + row * 16);
        #pragma unroll
        for (int c4 = 0; c4 < 8; c4++) {
            *(uint2*)(sQh + r * QPITCH + c4 * 8) = qh[c4];
            *(uint2*)(sQl + r * QPITCH + c4 * 8) = ql[c4];
        }
        const uint2* vhp = (const uint2*)(g_vh + row * 16);
        const uint2* vlp = (const uint2*)(g_vl + row * 16);
        #pragma unroll
        for (int c4 = 0; c4 < 8; c4++) {
            uint2 hv = vhp[c4], lv = vlp[c4];
            int d = c4 * 4;
            *(unsigned short*)(sVh + (d+0)*VPITCH + r*2) = (unsigned short)(hv.x & 0xFFFFu);
            *(unsigned short*)(sVh + (d+1)*VPITCH + r*2) = (unsigned short)(hv.x >> 16);
            *(unsigned short*)(sVh + (d+2)*VPITCH + r*2) = (unsigned short)(hv.y & 0xFFFFu);
            *(unsigned short*)(sVh + (d+3)*VPITCH + r*2) = (unsigned short)(hv.y >> 16);
            *(unsigned short*)(sVl + (d+0)*VPITCH + r*2) = (unsigned short)(lv.x & 0xFFFFu);
            *(unsigned short*)(sVl + (d+1)*VPITCH + r*2) = (unsigned short)(lv.x >> 16);
            *(unsigned short*)(sVl + (d+2)*VPITCH + r*2) = (unsigned short)(lv.y & 0xFFFFu);
            *(unsigned short*)(sVl + (d+3)*VPITCH + r*2) = (unsigned short)(lv.y >> 16);
        }
    }
    __syncthreads();

    int lane = tid & 31, w = tid >> 5;
    int r4 = lane >> 2, c4l = lane & 3;
    int mstart = 2 * w;
    int mcount = (w == 4) ? 1 : 2;
    int wi = b % num_win;
    u32 aQh = smem_u32(sQh), aQl = smem_u32(sQl);

    for (int mi = 0; mi < mcount; mi++) {
        int mt = mstart + mi;
        int row0 = mt * 16 + r4;

        u32 qh[2][4], ql[2][4];
        u32 arow = (u32)((mt * 16 + (lane & 15)) * QPITCH + ((lane >> 4) << 4));
        ldsm4(qh[0], aQh + arow);
        ldsm4(qh[1], aQh + arow + 32);
        ldsm4(ql[0], aQl + arow);
        ldsm4(ql[1], aQl + arow + 32);

        float sfr[18][4];
        #pragma unroll
        for (int j = 0; j < 18; j++)
            #pragma unroll
            for (int q = 0; q < 4; q++) sfr[j][q] = 0.0f;

        #pragma unroll
        for (int j = 0; j < 18; j++) {
            #pragma unroll
            for (int s = 0; s < 2; s++) {
                uint4 bb = *(const uint4*)(sKf + (((s * 18 + j) * 32 + lane) << 4));
                mma_bf16(sfr[j], qh[s], bb.x, bb.y);
                mma_bf16(sfr[j], ql[s], bb.x, bb.y);
                mma_bf16(sfr[j], qh[s], bb.z, bb.w);
            }
        }

        const float* bm0 = g_bm + (((size_t)h * num_win + wi) * LW + row0) * LW;
        const float* bm1 = bm0 + 8 * LW;
        float mx0 = -1e30f, mx1 = -1e30f;
        #pragma unroll
        for (int j = 0; j < 18; j++) {
            int col = j * 8 + c4l * 2;
            float2 b0 = *(const float2*)(bm0 + col);
            float2 b1 = *(const float2*)(bm1 + col);
            sfr[j][0] += b0.x; sfr[j][1] += b0.y;
            sfr[j][2] += b1.x; sfr[j][3] += b1.y;
            mx0 = fmaxf(mx0, fmaxf(sfr[j][0], sfr[j][1]));
            mx1 = fmaxf(mx1, fmaxf(sfr[j][2], sfr[j][3]));
        }
        mx0 = fmaxf(mx0, __shfl_xor_sync(0xFFFFFFFFu, mx0, 1));
        mx0 = fmaxf(mx0, __shfl_xor_sync(0xFFFFFFFFu, mx0, 2));
        mx1 = fmaxf(mx1, __shfl_xor_sync(0xFFFFFFFFu, mx1, 1));
        mx1 = fmaxf(mx1, __shfl_xor_sync(0xFFFFFFFFu, mx1, 2));

        float sum0 = 0.0f, sum1 = 0.0f;
        #pragma unroll
        for (int j = 0; j < 18; j++) {
            float p0 = fast_exp(sfr[j][0] - mx0);
            float p1 = fast_exp(sfr[j][1] - mx0);
            float p2 = fast_exp(sfr[j][2] - mx1);
            float p3 = fast_exp(sfr[j][3] - mx1);
            sfr[j][0] = p0; sfr[j][1] = p1; sfr[j][2] = p2; sfr[j][3] = p3;
            sum0 += p0 + p1; sum1 += p2 + p3;
        }
        sum0 += __shfl_xor_sync(0xFFFFFFFFu, sum0, 1);
        sum0 += __shfl_xor_sync(0xFFFFFFFFu, sum0, 2);
        sum1 += __shfl_xor_sync(0xFFFFFFFFu, sum1, 1);
        sum1 += __shfl_xor_sync(0xFFFFFFFFu, sum1, 2);

        float o[4][4];
        #pragma unroll
        for (int n = 0; n < 4; n++)
            #pragma unroll
            for (int q = 0; q < 4; q++) o[n][q] = 0.0f;

        #pragma unroll
        for (int t = 0; t < 9; t++) {
            u32 ph[4], pl[4];
            ph[0] = bf16x2_rn(sfr[2*t][0], sfr[2*t][1]);
            ph[1] = bf16x2_rn(sfr[2*t][2], sfr[2*t][3]);
            ph[2] = bf16x2_rn(sfr[2*t+1][0], sfr[2*t+1][1]);
            ph[3] = bf16x2_rn(sfr[2*t+1][2], sfr[2*t+1][3]);
            pl[0] = bf16x2_rn(sfr[2*t][0]   - __uint_as_float(ph[0] << 16),
                              sfr[2*t][1]   - __uint_as_float(ph[0] & 0xFFFF0000u));
            pl[1] = bf16x2_rn(sfr[2*t][2]   - __uint_as_float(ph[1] << 16),
                              sfr[2*t][3]   - __uint_as_float(ph[1] & 0xFFFF0000u));
            pl[2] = bf16x2_rn(sfr[2*t+1][0] - __uint_as_float(ph[2] << 16),
                              sfr[2*t+1][1] - __uint_as_float(ph[2] & 0xFFFF0000u));
            pl[3] = bf16x2_rn(sfr[2*t+1][2] - __uint_as_float(ph[3] << 16),
                              sfr[2*t+1][3] - __uint_as_float(ph[3] & 0xFFFF0000u));
            int kb = t * 32 + c4l * 4;
            #pragma unroll
            for (int n = 0; n < 4; n++) {
                int vrow = (n * 8 + r4) * VPITCH;
                u32 b0h = *(const u32*)(sVh + vrow + kb);
                u32 b1h = *(const u32*)(sVh + vrow + kb + 16);
                u32 b0l = *(const u32*)(sVl + vrow + kb);
                u32 b1l = *(const u32*)(sVl + vrow + kb + 16);
                mma_bf16(o[n], ph, b0h, b1h);
                mma_bf16(o[n], pl, b0h, b1h);
                mma_bf16(o[n], ph, b0l, b1l);
            }
        }

        float i0 = 1.0f / sum0, i1 = 1.0f / sum1;
        int m0r = b * LW + row0;
        int colb = h * DH + c4l * 2;
        #pragma unroll
        for (int n = 0; n < 4; n++) {
            int col = colb + n * 8;
            u32 hh, ll;
            split2(o[n][0] * i0, o[n][1] * i0, hh, ll);
            ((u32*)g_aoh)[(size_t)m0r * 128 + (col >> 1)] = hh;
            ((u32*)g_aol)[(size_t)m0r * 128 + (col >> 1)] = ll;
            split2(o[n][2] * i1, o[n][3] * i1, hh, ll);
            ((u32*)g_aoh)[(size_t)(m0r + 8) * 128 + (col >> 1)] = hh;
            ((u32*)g_aol)[(size_t)(m0r + 8) * 128 + (col >> 1)] = ll;
        }
    }
}

// ============================================================
// 4) Output projection
// ============================================================
__global__ void __launch_bounds__(256, 2)
proj_mma_kernel(const float* __restrict__ bias, float* __restrict__ out) {
    int m0 = blockIdx.y * 128;
    int n0b = blockIdx.x;
    float acc[2][8][4];
    gemm2(g_aoh, g_aol, g_wpf + (size_t)n0b * 8 * 4096, m0, acc);

    int lane = threadIdx.x & 31, wid = threadIdx.x >> 5;
    int wm = wid >> 1, wn = wid & 1;
    int r = lane >> 2, cp = (lane & 3) * 2;

    #pragma unroll
    for (int mt = 0; mt < 2; mt++) {
        #pragma unroll
        for (int half = 0; half < 2; half++) {
            int m = m0 + wm * 32 + mt * 16 + r + half * 8;
            #pragma unroll
            for (int nt2 = 0; nt2 < 8; nt2++) {
                int col = n0b * 128 + wn * 64 + nt2 * 8 + cp;
                float2 v;
                v.x = acc[mt][nt2][half * 2 + 0] + bias[col];
                v.y = acc[mt][nt2][half * 2 + 1] + bias[col + 1];
                *(float2*)(out + (size_t)m * CDIM + col) = v;
            }
        }
    }
}

// ============================================================
// launch
// ============================================================
extern "C" void kernel_launch(void* const* d_in, const int* in_sizes, int n_in,
                              void* d_out, int out_size) {
    const float* x           = (const float*)d_in[0];
    const float* mask        = (const float*)d_in[1];
    const float* qkv_w       = (const float*)d_in[2];
    const float* qkv_b       = (const float*)d_in[3];
    const float* proj_w      = (const float*)d_in[4];
    const float* proj_b      = (const float*)d_in[5];
    const float* fc1_w       = (const float*)d_in[6];
    const float* fc1_b       = (const float*)d_in[7];
    const float* fc2_w       = (const float*)d_in[8];
    const float* fc2_b       = (const float*)d_in[9];
    const float* logit_scale = (const float*)d_in[10];

    int Bw = in_sizes[0] / (LW * CDIM);       // 1024
    int num_win = in_sizes[1] / (LW * LW);    // 64
    int Mrows = Bw * LW;                      // 147456

    static int attr_set = 0;
    if (!attr_set) {
        cudaFuncSetAttribute(attn_mma_kernel,
                             cudaFuncAttributeMaxDynamicSharedMemorySize, ATTN_SMEM);
        cudaFuncSetAttribute(qkv_mma_kernel,
                             cudaFuncAttributeMaxDynamicSharedMemorySize, GEMM2_SMEM);
        cudaFuncSetAttribute(proj_mma_kernel,
                             cudaFuncAttributeMaxDynamicSharedMemorySize, GEMM2_SMEM);
        attr_set = 1;
    }

    int bm_total4 = HEADS * num_win * (LW * LW / 4);

    prep_kernel<<<PREP_GRID, 256>>>(x, qkv_w, proj_w, fc1_w, fc1_b, fc2_w, fc2_b);
    bm_kernel<<<(bm_total4 + 255) / 256, 256>>>(mask, num_win, bm_total4);
    qkv_mma_kernel<<<dim3(NQKV / 128, Mrows / 128), 256, GEMM2_SMEM>>>(qkv_b, logit_scale);
    attn_mma_kernel<<<Bw * HEADS, 160, ATTN_SMEM>>>(num_win);
    proj_mma_kernel<<<dim3(CDIM / 128, Mrows / 128), 256, GEMM2_SMEM>>>(proj_b, (float*)d_out);
}

// round 17
// speedup vs baseline: 1.5330x; 1.0113x over previous
#include <cuda_runtime.h>
#include <math.h>

typedef unsigned int       u32;
typedef unsigned long long u64;

// ---- problem constants ----
#define BW      1024
#define LW      144
#define CDIM    256
#define HEADS   8
#define DH      32
#define KDIM    256
#define NQKV    768
#define MH      384
#define LOGIT_MAX 4.605170185988091f
#define MROWS   (BW*LW)          // 147456
#define NWMAX   64

// ---- scratch (referenced ONLY inside device code) ----
__device__ float g_bias[HEADS*LW*LW];
__device__ float g_bm[HEADS*NWMAX*LW*LW];          // bias+mask fused
// x as bf16 hi/lo row-major
__device__ __align__(16) unsigned short g_xhi[MROWS*CDIM];
__device__ __align__(16) unsigned short g_xlo[MROWS*CDIM];
// q/k/v as bf16x2 hi/lo, normalized(+scaled) already: [(b*8+h)*144+l][16 u32]
__device__ __align__(16) u32 g_qh[BW*HEADS*LW*16];
__device__ __align__(16) u32 g_ql[BW*HEADS*LW*16];
__device__ __align__(16) u32 g_kh[BW*HEADS*LW*16];
__device__ __align__(16) u32 g_kl[BW*HEADS*LW*16];
__device__ __align__(16) u32 g_vh[BW*HEADS*LW*16];
__device__ __align__(16) u32 g_vl[BW*HEADS*LW*16];
// attention output bf16 hi/lo
__device__ __align__(16) unsigned short g_aoh[MROWS*CDIM];
__device__ __align__(16) unsigned short g_aol[MROWS*CDIM];
// weights pre-converted to B-fragment order: [nblock][kt][4096 u32]
__device__ __align__(16) u32 g_wqf[6*8*4096];
__device__ __align__(16) u32 g_wpf[2*8*4096];

// ============================================================
// helpers
// ============================================================
__device__ __forceinline__ float fast_exp(float x) {
    x = fmaxf(x, -87.0f);
    float y = x * 1.4426950408889634f;
    float n = rintf(y);
    float f = y - n;
    float p = 1.3333558146e-3f;
    p = fmaf(p, f, 9.6181291076e-3f);
    p = fmaf(p, f, 5.5504108664e-2f);
    p = fmaf(p, f, 2.4022650696e-1f);
    p = fmaf(p, f, 6.9314718056e-1f);
    p = fmaf(p, f, 1.0f);
    return p * __int_as_float(((int)n + 127) << 23);
}
__device__ __forceinline__ u32 smem_u32(const void* p) {
    u32 a;
    asm("{ .reg .u64 t; cvta.to.shared.u64 t, %1; cvt.u32.u64 %0, t; }" : "=r"(a) : "l"(p));
    return a;
}
__device__ __forceinline__ u32 bf16x2_rn(float lo, float hi) {
    u32 r; asm("cvt.rn.bf16x2.f32 %0, %1, %2;" : "=r"(r) : "f"(hi), "f"(lo)); return r;
}
__device__ __forceinline__ void ldsm4(u32* r, u32 addr) {
    asm volatile("ldmatrix.sync.aligned.m8n8.x4.shared.b16 {%0,%1,%2,%3}, [%4];"
        : "=r"(r[0]), "=r"(r[1]), "=r"(r[2]), "=r"(r[3]) : "r"(addr));
}
__device__ __forceinline__ void mma_bf16(float* d, const u32* a, u32 b0, u32 b1) {
    asm volatile("mma.sync.aligned.m16n8k16.row.col.f32.bf16.bf16.f32 "
        "{%0,%1,%2,%3}, {%4,%5,%6,%7}, {%8,%9}, {%0,%1,%2,%3};"
        : "+f"(d[0]), "+f"(d[1]), "+f"(d[2]), "+f"(d[3])
        : "r"(a[0]), "r"(a[1]), "r"(a[2]), "r"(a[3]), "r"(b0), "r"(b1));
}
__device__ __forceinline__ void cpa16(u32 dst, const void* src) {
    asm volatile("cp.async.cg.shared.global [%0], [%1], 16;" :: "r"(dst), "l"(src) : "memory");
}
__device__ __forceinline__ void split2(float x, float y, u32& h, u32& l) {
    h = bf16x2_rn(x, y);
    l = bf16x2_rn(x - __uint_as_float(h << 16), y - __uint_as_float(h & 0xFFFF0000u));
}

// ============================================================
// fused prep kernel: blockIdx ranges
// ============================================================
#define PREP_X_BLKS   36864
#define PREP_WQ_BLKS  192
#define PREP_WP_BLKS  64
#define PREP_B_BLKS   2592
#define PREP_GRID     (PREP_X_BLKS + PREP_WQ_BLKS + PREP_WP_BLKS + PREP_B_BLKS)

__device__ __forceinline__ void convert_w_body(const float* __restrict__ W,
                                               u32* __restrict__ dst, int i) {
    int nb  = i >> 13;
    int rem = i & 8191;
    int row = rem >> 6;
    int kt  = (rem >> 3) & 7;
    int c4  = rem & 7;
    float4 v = *(const float4*)(W + (size_t)(nb * 128 + row) * KDIM + kt * 32 + c4 * 4);
    u32 h01, l01, h23, l23;
    split2(v.x, v.y, h01, l01);
    split2(v.z, v.w, h23, l23);
    int s = c4 >> 2, khalf = (c4 >> 1) & 1;
    int l = ((row & 7) << 2) + ((c4 & 1) << 1);
    int nt = row >> 3;
    u32* base = dst + (size_t)(nb * 8 + kt) * 4096 + ((s * 16 + nt) * 32 + l) * 4;
    base[khalf]     = h01;
    base[2 + khalf] = l01;
    base[4 + khalf] = h23;
    base[6 + khalf] = l23;
}

__global__ void __launch_bounds__(256)
prep_kernel(const float* __restrict__ x,
            const float* __restrict__ qkv_w, const float* __restrict__ proj_w,
            const float* __restrict__ fc1_w, const float* __restrict__ fc1_b,
            const float* __restrict__ fc2_w, const float* __restrict__ fc2_b) {
    int bid = blockIdx.x;
    int tid = threadIdx.x;

    if (bid < PREP_X_BLKS) {
        size_t idx = (size_t)bid * 256 + tid;
        float4 v = ((const float4*)x)[idx];
        u32 h01, l01, h23, l23;
        split2(v.x, v.y, h01, l01);
        split2(v.z, v.w, h23, l23);
        ((uint2*)g_xhi)[idx] = make_uint2(h01, h23);
        ((uint2*)g_xlo)[idx] = make_uint2(l01, l23);
        return;
    }
    bid -= PREP_X_BLKS;
    if (bid < PREP_WQ_BLKS) {
        convert_w_body(qkv_w, g_wqf, bid * 256 + tid);
        return;
    }
    bid -= PREP_WQ_BLKS;
    if (bid < PREP_WP_BLKS) {
        convert_w_body(proj_w, g_wpf, bid * 256 + tid);
        return;
    }
    bid -= PREP_WP_BLKS;
    {
        int wid = tid >> 5, lane = tid & 31;
        int ij = bid * 8 + wid;
        int i = ij / LW, j = ij % LW;
        float dy = (float)(i / 12 - j / 12);
        float dx = (float)(i % 12 - j % 12);
        float ry = copysignf(log1pf(fabsf(dy)), dy);
        float rx = copysignf(log1pf(fabsf(dx)), dx);

        float a[HEADS];
        #pragma unroll
        for (int hh = 0; hh < HEADS; hh++) a[hh] = 0.0f;
        for (int t = lane; t < MH; t += 32) {
            float hs = fmaf(fc1_w[2*t], ry, fmaf(fc1_w[2*t+1], rx, fc1_b[t]));
            hs = fmaxf(hs, 0.0f);
            #pragma unroll
            for (int hh = 0; hh < HEADS; hh++)
                a[hh] = fmaf(fc2_w[hh*MH + t], hs, a[hh]);
        }
        #pragma unroll
        for (int hh = 0; hh < HEADS; hh++) {
            #pragma unroll
            for (int o = 16; o; o >>= 1)
                a[hh] += __shfl_xor_sync(0xFFFFFFFFu, a[hh], o);
        }
        if (lane < HEADS) {
            float outv = a[0];
            #pragma unroll
            for (int hh = 1; hh < HEADS; hh++)
                if (lane == hh) outv = a[hh];
            g_bias[lane*LW*LW + ij] = outv + fc2_b[lane];
        }
    }
}

// ============================================================
// 1b) fuse bias+mask
// ============================================================
__global__ void bm_kernel(const float* __restrict__ mask, int num_win, int total4) {
    int idx = blockIdx.x * 256 + threadIdx.x;
    if (idx >= total4) return;
    const int per = LW*LW/4;
    int hw = idx / per;
    int ij4 = idx % per;
    int h = hw / num_win, wi = hw % num_win;
    float4 bv = ((const float4*)(g_bias + h*LW*LW))[ij4];
    float4 mv = ((const float4*)(mask + (size_t)wi*LW*LW))[ij4];
    bv.x += mv.x; bv.y += mv.y; bv.z += mv.z; bv.w += mv.w;
    ((float4*)(g_bm + (size_t)hw*(LW*LW)))[ij4] = bv;
}

// ============================================================
// double-buffered cp.async GEMM mainloop (pre-converted operands)
// ============================================================
#define GSM_AHI    0
#define GSM_ALO    10240
#define GSM_BF     20480
#define GSM_STRIDE 36864
#define GEMM2_SMEM (2*GSM_STRIDE)

extern __shared__ char dynsm[];

__device__ __forceinline__ void gemm2_stage(const unsigned short* __restrict__ Ah,
                                            const unsigned short* __restrict__ Al,
                                            const u32* __restrict__ Wf,
                                            int m0, int kt, u32 s0) {
    int tid = threadIdx.x;
    #pragma unroll
    for (int j = 0; j < 2; j++) {
        int i = tid + j * 256;
        int r = i >> 2, c = i & 3;
        size_t so = (size_t)(m0 + r) * CDIM + kt * 32 + c * 8;
        cpa16(s0 + GSM_AHI + r * 80 + c * 16, Ah + so);
        cpa16(s0 + GSM_ALO + r * 80 + c * 16, Al + so);
    }
    const u32* wsrc = Wf + (size_t)kt * 4096;
    #pragma unroll
    for (int j = 0; j < 4; j++) {
        int i = tid + j * 256;
        cpa16(s0 + GSM_BF + i * 16, wsrc + i * 4);
    }
}

__device__ __forceinline__ void gemm2(const unsigned short* __restrict__ Ah,
                                      const unsigned short* __restrict__ Al,
                                      const u32* __restrict__ Wf,
                                      int m0, float acc[2][8][4]) {
    int tid = threadIdx.x, lane = tid & 31, wid = tid >> 5;
    int wm = wid >> 1, wn = wid & 1;

    #pragma unroll
    for (int mt = 0; mt < 2; mt++)
        #pragma unroll
        for (int nt = 0; nt < 8; nt++)
            #pragma unroll
            for (int c = 0; c < 4; c++) acc[mt][nt][c] = 0.0f;

    u32 sb = smem_u32(dynsm);
    gemm2_stage(Ah, Al, Wf, m0, 0, sb);
    asm volatile("cp.async.commit_group;" ::: "memory");

    for (int kt = 0; kt < 8; kt++) {
        if (kt < 7) {
            gemm2_stage(Ah, Al, Wf, m0, kt + 1, sb + ((kt + 1) & 1) * GSM_STRIDE);
            asm volatile("cp.async.commit_group;" ::: "memory");
            asm volatile("cp.async.wait_group 1;" ::: "memory");
        } else {
            asm volatile("cp.async.wait_group 0;" ::: "memory");
        }
        __syncthreads();

        u32 s0 = sb + (kt & 1) * GSM_STRIDE;
        u32 rowA = s0 + GSM_AHI + (wm * 32 + (lane & 15)) * 80 + ((lane >> 4) << 4);
        char* bfp = dynsm + (kt & 1) * GSM_STRIDE + GSM_BF;
        #pragma unroll
        for (int s = 0; s < 2; s++) {
            u32 ah[2][4], al[2][4];
            #pragma unroll
            for (int mt = 0; mt < 2; mt++) {
                u32 ad = rowA + mt * 16 * 80 + s * 32;
                ldsm4(ah[mt], ad);
                ldsm4(al[mt], ad + (GSM_ALO - GSM_AHI));
            }
            #pragma unroll
            for (int nt2 = 0; nt2 < 8; nt2++) {
                uint4 b = *(const uint4*)(bfp + (((s * 16 + wn * 8 + nt2) * 32 + lane) << 4));
                #pragma unroll
                for (int mt = 0; mt < 2; mt++) {
                    mma_bf16(acc[mt][nt2], ah[mt], b.x, b.y);
                    mma_bf16(acc[mt][nt2], al[mt], b.x, b.y);
                    mma_bf16(acc[mt][nt2], ah[mt], b.z, b.w);
                }
            }
        }
        __syncthreads();
    }
}

// ============================================================
// 2) QKV GEMM: epilogue does bias add + normalize + scale + bf16 split.
// ============================================================
__global__ void __launch_bounds__(256, 2)
qkv_mma_kernel(const float* __restrict__ bias, const float* __restrict__ logit_scale) {
    int m0 = blockIdx.y * 128;
    int n0b = blockIdx.x;
    float acc[2][8][4];
    gemm2(g_xhi, g_xlo, g_wqf + (size_t)n0b * 8 * 4096, m0, acc);

    int lane = threadIdx.x & 31, wid = threadIdx.x >> 5;
    int wm = wid >> 1, wn = wid & 1;
    int r = lane >> 2, c4l = lane & 3, cp = c4l * 2;
    int part = n0b >> 1;   // 0=q 1=k 2=v
    u32 *dh, *dl;
    if (part == 0)      { dh = g_qh; dl = g_ql; }
    else if (part == 1) { dh = g_kh; dl = g_kl; }
    else                { dh = g_vh; dl = g_vl; }

    #pragma unroll
    for (int mt = 0; mt < 2; mt++) {
        #pragma unroll
        for (int half = 0; half < 2; half++) {
            int m = m0 + wm * 32 + mt * 16 + r + half * 8;
            int b = m / LW, l = m % LW;
            #pragma unroll
            for (int g = 0; g < 2; g++) {
                int h = (n0b & 1) * 4 + wn * 2 + g;
                float v[8];
                #pragma unroll
                for (int j = 0; j < 4; j++) {
                    int col = n0b * 128 + wn * 64 + (g * 4 + j) * 8 + cp;
                    v[2*j]   = acc[mt][g*4+j][half*2]   + bias[col];
                    v[2*j+1] = acc[mt][g*4+j][half*2+1] + bias[col+1];
                }
                float inv = 1.0f;
                if (part < 2) {
                    float ss = 0.0f;
                    #pragma unroll
                    for (int q = 0; q < 8; q++) ss = fmaf(v[q], v[q], ss);
                    ss += __shfl_xor_sync(0xFFFFFFFFu, ss, 1);
                    ss += __shfl_xor_sync(0xFFFFFFFFu, ss, 2);
                    inv = 1.0f / fmaxf(sqrtf(ss), 1e-12f);
                    if (part == 0)
                        inv *= fast_exp(fminf(logit_scale[h], LOGIT_MAX));
                }
                size_t row = (size_t)(b * HEADS + h) * LW + l;
                #pragma unroll
                for (int j = 0; j < 4; j++) {
                    u32 hh, ll;
                    split2(v[2*j] * inv, v[2*j+1] * inv, hh, ll);
                    dh[row * 16 + j * 4 + c4l] = hh;
                    dl[row * 16 + j * 4 + c4l] = ll;
                }
            }
        }
    }
}

// ============================================================
// 3) Attention: flash-style mma.sync bf16x3 (R12 body; minBlocks=3)
// ============================================================
#define QPITCH 80
#define VPITCH 304
#define OQH 0
#define OQL 11520
#define OKF 23040
#define OVH 41472
#define OVL 51200
#define ATTN_SMEM 60928

__global__ void __launch_bounds__(160, 3)
attn_mma_kernel(int num_win) {
    extern __shared__ char sm[];
    char* sQh = sm + OQH;
    char* sQl = sm + OQL;
    char* sKf = sm + OKF;
    char* sVh = sm + OVH;
    char* sVl = sm + OVL;

    int h = blockIdx.x & 7;
    int b = blockIdx.x >> 3;
    int tid = threadIdx.x;

    if (tid < LW) {
        int r = tid;
        size_t row = (size_t)(b * HEADS + h) * LW + r;
        const uint2* kh = (const uint2*)(g_kh + row * 16);
        const uint2* kl = (const uint2*)(g_kl + row * 16);
        #pragma unroll
        for (int c4 = 0; c4 < 8; c4++) {
            uint2 vh = kh[c4], vl = kl[c4];
            int s = c4 >> 2, khalf = (c4 >> 1) & 1;
            int l = ((r & 7) << 2) + ((c4 & 1) << 1);
            int nt = r >> 3;
            char* p = sKf + (((s * 18 + nt) * 32 + l) << 4);
            *(u32*)(p + khalf * 4)      = vh.x;
            *(u32*)(p + 8 + khalf * 4)  = vl.x;
            *(u32*)(p + 16 + khalf * 4) = vh.y;
            *(u32*)(p + 24 + khalf * 4) = vl.y;
        }
        const uint2* qh = (const uint2*)(g_qh + row * 16);
        const uint2* ql = (const uint2*)(g_ql + row * 16);
        #pragma unroll
        for (int c4 = 0; c4 < 8; c4++) {
            *(uint2*)(sQh + r * QPITCH + c4 * 8) = qh[c4];
            *(uint2*)(sQl + r * QPITCH + c4 * 8) = ql[c4];
        }
        const uint2* vhp = (const uint2*)(g_vh + row * 16);
        const uint2* vlp = (const uint2*)(g_vl + row * 16);
        #pragma unroll
        for (int c4 = 0; c4 < 8; c4++) {
            uint2 hv = vhp[c4], lv = vlp[c4];
            int d = c4 * 4;
            *(unsigned short*)(sVh + (d+0)*VPITCH + r*2) = (unsigned short)(hv.x & 0xFFFFu);
            *(unsigned short*)(sVh + (d+1)*VPITCH + r*2) = (unsigned short)(hv.x >> 16);
            *(unsigned short*)(sVh + (d+2)*VPITCH + r*2) = (unsigned short)(hv.y & 0xFFFFu);
            *(unsigned short*)(sVh + (d+3)*VPITCH + r*2) = (unsigned short)(hv.y >> 16);
            *(unsigned short*)(sVl + (d+0)*VPITCH + r*2) = (unsigned short)(lv.x & 0xFFFFu);
            *(unsigned short*)(sVl + (d+1)*VPITCH + r*2) = (unsigned short)(lv.x >> 16);
            *(unsigned short*)(sVl + (d+2)*VPITCH + r*2) = (unsigned short)(lv.y & 0xFFFFu);
            *(unsigned short*)(sVl + (d+3)*VPITCH + r*2) = (unsigned short)(lv.y >> 16);
        }
    }
    __syncthreads();

    int lane = tid & 31, w = tid >> 5;
    int r4 = lane >> 2, c4l = lane & 3;
    int mstart = 2 * w;
    int mcount = (w == 4) ? 1 : 2;
    int wi = b % num_win;
    u32 aQh = smem_u32(sQh), aQl = smem_u32(sQl);

    for (int mi = 0; mi < mcount; mi++) {
        int mt = mstart + mi;
        int row0 = mt * 16 + r4;

        u32 qh[2][4], ql[2][4];
        u32 arow = (u32)((mt * 16 + (lane & 15)) * QPITCH + ((lane >> 4) << 4));
        ldsm4(qh[0], aQh + arow);
        ldsm4(qh[1], aQh + arow + 32);
        ldsm4(ql[0], aQl + arow);
        ldsm4(ql[1], aQl + arow + 32);

        float sfr[18][4];
        #pragma unroll
        for (int j = 0; j < 18; j++)
            #pragma unroll
            for (int q = 0; q < 4; q++) sfr[j][q] = 0.0f;

        #pragma unroll
        for (int j = 0; j < 18; j++) {
            #pragma unroll
            for (int s = 0; s < 2; s++) {
                uint4 bb = *(const uint4*)(sKf + (((s * 18 + j) * 32 + lane) << 4));
                mma_bf16(sfr[j], qh[s], bb.x, bb.y);
                mma_bf16(sfr[j], ql[s], bb.x, bb.y);
                mma_bf16(sfr[j], qh[s], bb.z, bb.w);
            }
        }

        const float* bm0 = g_bm + (((size_t)h * num_win + wi) * LW + row0) * LW;
        const float* bm1 = bm0 + 8 * LW;
        float mx0 = -1e30f, mx1 = -1e30f;
        #pragma unroll
        for (int j = 0; j < 18; j++) {
            int col = j * 8 + c4l * 2;
            float2 b0 = *(const float2*)(bm0 + col);
            float2 b1 = *(const float2*)(bm1 + col);
            sfr[j][0] += b0.x; sfr[j][1] += b0.y;
            sfr[j][2] += b1.x; sfr[j][3] += b1.y;
            mx0 = fmaxf(mx0, fmaxf(sfr[j][0], sfr[j][1]));
            mx1 = fmaxf(mx1, fmaxf(sfr[j][2], sfr[j][3]));
        }
        mx0 = fmaxf(mx0, __shfl_xor_sync(0xFFFFFFFFu, mx0, 1));
        mx0 = fmaxf(mx0, __shfl_xor_sync(0xFFFFFFFFu, mx0, 2));
        mx1 = fmaxf(mx1, __shfl_xor_sync(0xFFFFFFFFu, mx1, 1));
        mx1 = fmaxf(mx1, __shfl_xor_sync(0xFFFFFFFFu, mx1, 2));

        float sum0 = 0.0f, sum1 = 0.0f;
        #pragma unroll
        for (int j = 0; j < 18; j++) {
            float p0 = fast_exp(sfr[j][0] - mx0);
            float p1 = fast_exp(sfr[j][1] - mx0);
            float p2 = fast_exp(sfr[j][2] - mx1);
            float p3 = fast_exp(sfr[j][3] - mx1);
            sfr[j][0] = p0; sfr[j][1] = p1; sfr[j][2] = p2; sfr[j][3] = p3;
            sum0 += p0 + p1; sum1 += p2 + p3;
        }
        sum0 += __shfl_xor_sync(0xFFFFFFFFu, sum0, 1);
        sum0 += __shfl_xor_sync(0xFFFFFFFFu, sum0, 2);
        sum1 += __shfl_xor_sync(0xFFFFFFFFu, sum1, 1);
        sum1 += __shfl_xor_sync(0xFFFFFFFFu, sum1, 2);

        float o[4][4];
        #pragma unroll
        for (int n = 0; n < 4; n++)
            #pragma unroll
            for (int q = 0; q < 4; q++) o[n][q] = 0.0f;

        #pragma unroll
        for (int t = 0; t < 9; t++) {
            u32 ph[4], pl[4];
            ph[0] = bf16x2_rn(sfr[2*t][0], sfr[2*t][1]);
            ph[1] = bf16x2_rn(sfr[2*t][2], sfr[2*t][3]);
            ph[2] = bf16x2_rn(sfr[2*t+1][0], sfr[2*t+1][1]);
            ph[3] = bf16x2_rn(sfr[2*t+1][2], sfr[2*t+1][3]);
            pl[0] = bf16x2_rn(sfr[2*t][0]   - __uint_as_float(ph[0] << 16),
                              sfr[2*t][1]   - __uint_as_float(ph[0] & 0xFFFF0000u));
            pl[1] = bf16x2_rn(sfr[2*t][2]   - __uint_as_float(ph[1] << 16),
                              sfr[2*t][3]   - __uint_as_float(ph[1] & 0xFFFF0000u));
            pl[2] = bf16x2_rn(sfr[2*t+1][0] - __uint_as_float(ph[2] << 16),
                              sfr[2*t+1][1] - __uint_as_float(ph[2] & 0xFFFF0000u));
            pl[3] = bf16x2_rn(sfr[2*t+1][2] - __uint_as_float(ph[3] << 16),
                              sfr[2*t+1][3] - __uint_as_float(ph[3] & 0xFFFF0000u));
            int kb = t * 32 + c4l * 4;
            #pragma unroll
            for (int n = 0; n < 4; n++) {
                int vrow = (n * 8 + r4) * VPITCH;
                u32 b0h = *(const u32*)(sVh + vrow + kb);
                u32 b1h = *(const u32*)(sVh + vrow + kb + 16);
                u32 b0l = *(const u32*)(sVl + vrow + kb);
                u32 b1l = *(const u32*)(sVl + vrow + kb + 16);
                mma_bf16(o[n], ph, b0h, b1h);
                mma_bf16(o[n], pl, b0h, b1h);
                mma_bf16(o[n], ph, b0l, b1l);
            }
        }

        float i0 = 1.0f / sum0, i1 = 1.0f / sum1;
        int m0r = b * LW + row0;
        int colb = h * DH + c4l * 2;
        #pragma unroll
        for (int n = 0; n < 4; n++) {
            int col = colb + n * 8;
            u32 hh, ll;
            split2(o[n][0] * i0, o[n][1] * i0, hh, ll);
            ((u32*)g_aoh)[(size_t)m0r * 128 + (col >> 1)] = hh;
            ((u32*)g_aol)[(size_t)m0r * 128 + (col >> 1)] = ll;
            split2(o[n][2] * i1, o[n][3] * i1, hh, ll);
            ((u32*)g_aoh)[(size_t)(m0r + 8) * 128 + (col >> 1)] = hh;
            ((u32*)g_aol)[(size_t)(m0r + 8) * 128 + (col >> 1)] = ll;
        }
    }
}

// ============================================================
// 4) Output projection
// ============================================================
__global__ void __launch_bounds__(256, 2)
proj_mma_kernel(const float* __restrict__ bias, float* __restrict__ out) {
    int m0 = blockIdx.y * 128;
    int n0b = blockIdx.x;
    float acc[2][8][4];
    gemm2(g_aoh, g_aol, g_wpf + (size_t)n0b * 8 * 4096, m0, acc);

    int lane = threadIdx.x & 31, wid = threadIdx.x >> 5;
    int wm = wid >> 1, wn = wid & 1;
    int r = lane >> 2, cp = (lane & 3) * 2;

    #pragma unroll
    for (int mt = 0; mt < 2; mt++) {
        #pragma unroll
        for (int half = 0; half < 2; half++) {
            int m = m0 + wm * 32 + mt * 16 + r + half * 8;
            #pragma unroll
            for (int nt2 = 0; nt2 < 8; nt2++) {
                int col = n0b * 128 + wn * 64 + nt2 * 8 + cp;
                float2 v;
                v.x = acc[mt][nt2][half * 2 + 0] + bias[col];
                v.y = acc[mt][nt2][half * 2 + 1] + bias[col + 1];
                *(float2*)(out + (size_t)m * CDIM + col) = v;
            }
        }
    }
}

// ============================================================
// launch
// ============================================================
extern "C" void kernel_launch(void* const* d_in, const int* in_sizes, int n_in,
                              void* d_out, int out_size) {
    const float* x           = (const float*)d_in[0];
    const float* mask        = (const float*)d_in[1];
    const float* qkv_w       = (const float*)d_in[2];
    const float* qkv_b       = (const float*)d_in[3];
    const float* proj_w      = (const float*)d_in[4];
    const float* proj_b      = (const float*)d_in[5];
    const float* fc1_w       = (const float*)d_in[6];
    const float* fc1_b       = (const float*)d_in[7];
    const float* fc2_w       = (const float*)d_in[8];
    const float* fc2_b       = (const float*)d_in[9];
    const float* logit_scale = (const float*)d_in[10];

    int Bw = in_sizes[0] / (LW * CDIM);       // 1024
    int num_win = in_sizes[1] / (LW * LW);    // 64
    int Mrows = Bw * LW;                      // 147456

    static int attr_set = 0;
    if (!attr_set) {
        cudaFuncSetAttribute(attn_mma_kernel,
                             cudaFuncAttributeMaxDynamicSharedMemorySize, ATTN_SMEM);
        cudaFuncSetAttribute(qkv_mma_kernel,
                             cudaFuncAttributeMaxDynamicSharedMemorySize, GEMM2_SMEM);
        cudaFuncSetAttribute(proj_mma_kernel,
                             cudaFuncAttributeMaxDynamicSharedMemorySize, GEMM2_SMEM);
        attr_set = 1;
    }

    int bm_total4 = HEADS * num_win * (LW * LW / 4);

    prep_kernel<<<PREP_GRID, 256>>>(x, qkv_w, proj_w, fc1_w, fc1_b, fc2_w, fc2_b);
    bm_kernel<<<(bm_total4 + 255) / 256, 256>>>(mask, num_win, bm_total4);
    qkv_mma_kernel<<<dim3(NQKV / 128, Mrows / 128), 256, GEMM2_SMEM>>>(qkv_b, logit_scale);
    attn_mma_kernel<<<Bw * HEADS, 160, ATTN_SMEM>>>(num_win);
    proj_mma_kernel<<<dim3(CDIM / 128, Mrows / 128), 256, GEMM2_SMEM>>>(proj_b, (float*)d_out);
}